// round 6
// baseline (speedup 1.0000x reference)
#include <cuda_runtime.h>

#define N_NODES 40000
#define N_EDGES 640000
#define F 128
#define FV (F / 4)   // float4 per row

// ---------------- scratch (device globals: no allocation allowed) ----------
__device__ float  g_deg[N_NODES];
__device__ float  g_dis[N_NODES];
__device__ int    g_cnt[N_NODES];
__device__ int    g_rowptr[N_NODES + 1];
__device__ int    g_cur[N_NODES];
__device__ int2   g_edge[N_EDGES];             // .x = src node, .y = norm (float bits)
__device__ float4 g_y1[(size_t)N_NODES * FV];  // hop-1 result
__device__ float4 g_y2[(size_t)N_NODES * FV];  // hop-2 result
__device__ int    g_is64;                      // 1 if edge_index stored as int64

// ---------------- init + edge-index width detect ---------------------------
// ids in [0, 40000): if stored little-endian int64 every odd 32-bit word is 0.
__global__ void init_kernel(const int* __restrict__ e32) {
    int i = blockIdx.x * blockDim.x + threadIdx.x;
    if (i < N_NODES) { g_deg[i] = 1.0f; g_cnt[i] = 0; }
    if (i == 0) {
        int all_zero = 1;
        for (int k = 0; k < 16; k++)
            if (e32[2 * k + 1] != 0) all_zero = 0;
        g_is64 = all_zero;
    }
}

__device__ __forceinline__ int edge_src(const int* e32, int e) {
    return g_is64 ? e32[2 * e] : e32[e];
}
__device__ __forceinline__ int edge_dst(const int* e32, int e) {
    return g_is64 ? e32[2 * N_EDGES + 2 * e] : e32[N_EDGES + e];
}

// ---------------- degree + in-edge histogram over real edges ---------------
__global__ void deg_kernel(const int* __restrict__ e32, const float* __restrict__ w) {
    int e = blockIdx.x * blockDim.x + threadIdx.x;
    if (e < N_EDGES) {
        int c = edge_dst(e32, e);
        if ((unsigned)c < N_NODES) {
            atomicAdd(&g_deg[c], w[e]);
            atomicAdd(&g_cnt[c], 1);
        }
    }
}

// ---------------- exclusive scan of histogram -> rowptr / cursors + dis ----
__global__ void scan_kernel() {
    __shared__ int sums[1024];
    int t = threadIdx.x;
    const int CH = (N_NODES + 1023) / 1024;   // 40
    int beg = t * CH;
    int end = min(beg + CH, N_NODES);
    int s = 0;
    for (int i = beg; i < end; i++) {
        s += g_cnt[i];
        g_dis[i] = rsqrtf(g_deg[i]);          // deg >= 1 always (self loop)
    }
    sums[t] = s;
    __syncthreads();
    for (int off = 1; off < 1024; off <<= 1) {
        int v = sums[t];
        int add = (t >= off) ? sums[t - off] : 0;
        __syncthreads();
        sums[t] = v + add;
        __syncthreads();
    }
    int run = (t == 0) ? 0 : sums[t - 1];
    for (int i = beg; i < end; i++) {
        g_rowptr[i] = run;
        g_cur[i]    = run;
        run += g_cnt[i];
    }
    if (t == 0) g_rowptr[N_NODES] = sums[1023];
}

// ---------------- scatter edges into CSR slots, precompute norm ------------
__global__ void scatter_kernel(const int* __restrict__ e32, const float* __restrict__ w) {
    int e = blockIdx.x * blockDim.x + threadIdx.x;
    if (e < N_EDGES) {
        int r = edge_src(e32, e);
        int c = edge_dst(e32, e);
        if ((unsigned)r < N_NODES && (unsigned)c < N_NODES) {
            int p = atomicAdd(&g_cur[c], 1);
            float nm = g_dis[r] * w[e] * g_dis[c];
            g_edge[p] = make_int2(r, __float_as_int(nm));
        }
    }
}

// ---------------- one propagation hop: warp per node, float4 per lane ------
// Dependent edge->gather chain with modest unroll: warp-level parallelism
// (not per-warp MLP) hides L2 latency; deeper per-warp batching regressed
// (L1tex queue contention, round-5 measurement).
__device__ __forceinline__ void prop_body(const float4* __restrict__ xin,
                                          float4* __restrict__ xout) {
    int node = (blockIdx.x * blockDim.x + threadIdx.x) >> 5;
    int lane = threadIdx.x & 31;
    if (node >= N_NODES) return;
    float dis = g_dis[node];
    float sl = dis * dis;                      // self-loop norm
    float4 v = xin[(size_t)node * FV + lane];
    float4 acc = make_float4(sl * v.x, sl * v.y, sl * v.z, sl * v.w);
    int beg = g_rowptr[node];
    int end = g_rowptr[node + 1];
#pragma unroll 2
    for (int e = beg; e < end; e++) {
        int2 ed = __ldg(&g_edge[e]);           // broadcast across warp
        float nm = __int_as_float(ed.y);
        float4 xv = xin[(size_t)ed.x * FV + lane];
        acc.x += nm * xv.x;
        acc.y += nm * xv.y;
        acc.z += nm * xv.z;
        acc.w += nm * xv.w;
    }
    xout[(size_t)node * FV + lane] = acc;
}

__global__ void __launch_bounds__(256) prop1_kernel(const float4* __restrict__ xin) {
    prop_body(xin, g_y1);
}
__global__ void __launch_bounds__(256) prop2_kernel() {
    prop_body(g_y1, g_y2);
}

// ---------------- dense linear: out = g_y2 @ W^T + b -----------------------
// Block: 256 threads, tile 64 rows x 128 cols. Thread = 8 rows x 4 cols.
#define GM_TM 64
#define GM_KT 16
__global__ void __launch_bounds__(256) gemm_kernel(const float4* __restrict__ Wm4,
                                                   const float* __restrict__ bias,
                                                   float* __restrict__ out) {
    __shared__ float xs[GM_KT][GM_TM + 1];   // [k][row], padded
    __shared__ float ws[GM_KT][F];           // [k][ocol]
    int t  = threadIdx.x;
    int ci = t & 31;     // col group -> cols 4*ci .. 4*ci+3
    int ri = t >> 5;     // row group -> rows 8*ri .. 8*ri+7
    int row0 = blockIdx.x * GM_TM;

    float acc[8][4];
#pragma unroll
    for (int i = 0; i < 8; i++)
#pragma unroll
        for (int j = 0; j < 4; j++) acc[i][j] = 0.0f;

    for (int k0 = 0; k0 < F; k0 += GM_KT) {
        {
            int r  = t >> 2;
            int kq = (t & 3) * 4;
            float4 v = g_y2[(size_t)(row0 + r) * FV + (k0 + kq) / 4];
            xs[kq + 0][r] = v.x; xs[kq + 1][r] = v.y;
            xs[kq + 2][r] = v.z; xs[kq + 3][r] = v.w;
        }
#pragma unroll
        for (int l = 0; l < 2; l++) {
            int idx = t + l * 256;
            int o   = idx >> 2;
            int kq  = (idx & 3) * 4;
            float4 v = Wm4[((size_t)o * F + k0 + kq) / 4];
            ws[kq + 0][o] = v.x; ws[kq + 1][o] = v.y;
            ws[kq + 2][o] = v.z; ws[kq + 3][o] = v.w;
        }
        __syncthreads();
#pragma unroll
        for (int kk = 0; kk < GM_KT; kk++) {
            float a[8];
#pragma unroll
            for (int j = 0; j < 8; j++) a[j] = xs[kk][ri * 8 + j];       // broadcast
            float b0 = ws[kk][ci * 4 + 0];
            float b1 = ws[kk][ci * 4 + 1];
            float b2 = ws[kk][ci * 4 + 2];
            float b3 = ws[kk][ci * 4 + 3];
#pragma unroll
            for (int i = 0; i < 8; i++) {
                acc[i][0] += a[i] * b0;
                acc[i][1] += a[i] * b1;
                acc[i][2] += a[i] * b2;
                acc[i][3] += a[i] * b3;
            }
        }
        __syncthreads();
    }

#pragma unroll
    for (int i = 0; i < 8; i++) {
        int r = row0 + ri * 8 + i;
        int c = ci * 4;
        float4 v = make_float4(acc[i][0] + bias[c + 0], acc[i][1] + bias[c + 1],
                               acc[i][2] + bias[c + 2], acc[i][3] + bias[c + 3]);
        *(float4*)&out[(size_t)r * F + c] = v;
    }
}

// ---------------------------------------------------------------------------
extern "C" void kernel_launch(void* const* d_in, const int* in_sizes, int n_in,
                              void* d_out, int out_size) {
    const float* x   = (const float*)d_in[0];
    const int*   e32 = (const int*)d_in[1];    // edge_index, width auto-detected
    const float* w   = (const float*)d_in[2];
    const float* Wm  = (const float*)d_in[3];
    const float* b   = (const float*)d_in[4];
    float* out = (float*)d_out;

    const int TB = 256;
    init_kernel<<<(N_NODES + TB - 1) / TB, TB>>>(e32);
    deg_kernel<<<(N_EDGES + TB - 1) / TB, TB>>>(e32, w);
    scan_kernel<<<1, 1024>>>();
    scatter_kernel<<<(N_EDGES + TB - 1) / TB, TB>>>(e32, w);

    // two propagation hops (warp per node, 8 warps per block)
    prop1_kernel<<<N_NODES / 8, 256>>>((const float4*)x);
    prop2_kernel<<<N_NODES / 8, 256>>>();

    gemm_kernel<<<N_NODES / GM_TM, 256>>>((const float4*)Wm, b, out);
}

// round 7
// speedup vs baseline: 1.2461x; 1.2461x over previous
#include <cuda_runtime.h>
#include <cuda_fp16.h>

#define N_NODES 40000
#define N_EDGES 640000
#define F 128
#define FV (F / 4)    // float4 per row
#define FH (F / 4)    // uint2 (4 halfs) per row -> 32 per row

// ---------------- scratch (device globals: no allocation allowed) ----------
__device__ float  g_deg[N_NODES];
__device__ float  g_dis[N_NODES];
__device__ int    g_cnt[N_NODES];
__device__ int    g_rowptr[N_NODES + 1];
__device__ int    g_cur[N_NODES];
__device__ int2   g_edge[N_EDGES];              // .x = src node, .y = norm (float bits)
__device__ uint2  g_xh [(size_t)N_NODES * 32];  // x in fp16 (4 halfs per uint2)
__device__ uint2  g_y1h[(size_t)N_NODES * 32];  // hop-1 result in fp16
__device__ float4 g_y2 [(size_t)N_NODES * FV];  // hop-2 result fp32 (GEMM input)
__device__ int    g_is64;                       // 1 if edge_index stored as int64

// ---------------- init + edge-index width detect ---------------------------
__global__ void init_kernel(const int* __restrict__ e32) {
    int i = blockIdx.x * blockDim.x + threadIdx.x;
    if (i < N_NODES) { g_deg[i] = 1.0f; g_cnt[i] = 0; }
    if (i == 0) {
        int all_zero = 1;
        for (int k = 0; k < 16; k++)
            if (e32[2 * k + 1] != 0) all_zero = 0;
        g_is64 = all_zero;
    }
}

__device__ __forceinline__ int edge_src(const int* e32, int e) {
    return g_is64 ? e32[2 * e] : e32[e];
}
__device__ __forceinline__ int edge_dst(const int* e32, int e) {
    return g_is64 ? e32[2 * N_EDGES + 2 * e] : e32[N_EDGES + e];
}

// ---------------- convert x (fp32) -> g_xh (fp16) --------------------------
__global__ void tohalf_kernel(const float4* __restrict__ x4) {
    int i = blockIdx.x * blockDim.x + threadIdx.x;   // one float4 -> one uint2
    if (i < N_NODES * FV) {
        float4 v = x4[i];
        __half2 h0 = __floats2half2_rn(v.x, v.y);
        __half2 h1 = __floats2half2_rn(v.z, v.w);
        uint2 o;
        o.x = *(unsigned*)&h0;
        o.y = *(unsigned*)&h1;
        ((uint2*)g_xh)[i] = o;
    }
}

// ---------------- degree + in-edge histogram over real edges ---------------
__global__ void deg_kernel(const int* __restrict__ e32, const float* __restrict__ w) {
    int e = blockIdx.x * blockDim.x + threadIdx.x;
    if (e < N_EDGES) {
        int c = edge_dst(e32, e);
        if ((unsigned)c < N_NODES) {
            atomicAdd(&g_deg[c], w[e]);
            atomicAdd(&g_cnt[c], 1);
        }
    }
}

__global__ void dis_kernel() {
    int i = blockIdx.x * blockDim.x + threadIdx.x;
    if (i < N_NODES) g_dis[i] = rsqrtf(g_deg[i]);   // deg >= 1 (self loop)
}

// ---------------- exclusive scan of histogram -> rowptr / cursors ----------
__global__ void scan_kernel() {
    __shared__ int sums[1024];
    int t = threadIdx.x;
    const int CH = (N_NODES + 1023) / 1024;   // 40
    int beg = t * CH;
    int end = min(beg + CH, N_NODES);
    int s = 0;
    for (int i = beg; i < end; i++) s += g_cnt[i];
    sums[t] = s;
    __syncthreads();
    for (int off = 1; off < 1024; off <<= 1) {
        int v = sums[t];
        int add = (t >= off) ? sums[t - off] : 0;
        __syncthreads();
        sums[t] = v + add;
        __syncthreads();
    }
    int run = (t == 0) ? 0 : sums[t - 1];
    for (int i = beg; i < end; i++) {
        g_rowptr[i] = run;
        g_cur[i]    = run;
        run += g_cnt[i];
    }
    if (t == 0) g_rowptr[N_NODES] = sums[1023];
}

// ---------------- scatter edges into CSR slots, precompute norm ------------
__global__ void scatter_kernel(const int* __restrict__ e32, const float* __restrict__ w) {
    int e = blockIdx.x * blockDim.x + threadIdx.x;
    if (e < N_EDGES) {
        int r = edge_src(e32, e);
        int c = edge_dst(e32, e);
        if ((unsigned)r < N_NODES && (unsigned)c < N_NODES) {
            int p = atomicAdd(&g_cur[c], 1);
            float nm = g_dis[r] * w[e] * g_dis[c];
            g_edge[p] = make_int2(r, __float_as_int(nm));
        }
    }
}

// ---------------- gather helper: 4 fp16 features -> fp32 -------------------
__device__ __forceinline__ void gather_h(const uint2* __restrict__ xh, int node, int lane,
                                         float& f0, float& f1, float& f2, float& f3) {
    uint2 r = __ldg(&xh[(size_t)node * 32 + lane]);
    __half2 a = *(__half2*)&r.x;
    __half2 b = *(__half2*)&r.y;
    float2 fa = __half22float2(a);
    float2 fb = __half22float2(b);
    f0 = fa.x; f1 = fa.y; f2 = fb.x; f3 = fb.y;
}

// ---------------- hop 1: gather fp16 x, write fp16 y1 ----------------------
__global__ void __launch_bounds__(256) prop1_kernel() {
    int node = (blockIdx.x * blockDim.x + threadIdx.x) >> 5;
    int lane = threadIdx.x & 31;
    if (node >= N_NODES) return;
    float dis = g_dis[node];
    float sl = dis * dis;
    float v0, v1, v2, v3;
    gather_h(g_xh, node, lane, v0, v1, v2, v3);
    float ax = sl * v0, ay = sl * v1, az = sl * v2, aw = sl * v3;
    int beg = g_rowptr[node];
    int end = g_rowptr[node + 1];
#pragma unroll 2
    for (int e = beg; e < end; e++) {
        int2 ed = __ldg(&g_edge[e]);           // broadcast across warp
        float nm = __int_as_float(ed.y);
        float x0, x1, x2, x3;
        gather_h(g_xh, ed.x, lane, x0, x1, x2, x3);
        ax += nm * x0; ay += nm * x1; az += nm * x2; aw += nm * x3;
    }
    __half2 o0 = __floats2half2_rn(ax, ay);
    __half2 o1 = __floats2half2_rn(az, aw);
    uint2 o;
    o.x = *(unsigned*)&o0;
    o.y = *(unsigned*)&o1;
    g_y1h[(size_t)node * 32 + lane] = o;
}

// ---------------- hop 2: gather fp16 y1, write fp32 y2 ---------------------
__global__ void __launch_bounds__(256) prop2_kernel() {
    int node = (blockIdx.x * blockDim.x + threadIdx.x) >> 5;
    int lane = threadIdx.x & 31;
    if (node >= N_NODES) return;
    float dis = g_dis[node];
    float sl = dis * dis;
    float v0, v1, v2, v3;
    gather_h(g_y1h, node, lane, v0, v1, v2, v3);
    float ax = sl * v0, ay = sl * v1, az = sl * v2, aw = sl * v3;
    int beg = g_rowptr[node];
    int end = g_rowptr[node + 1];
#pragma unroll 2
    for (int e = beg; e < end; e++) {
        int2 ed = __ldg(&g_edge[e]);
        float nm = __int_as_float(ed.y);
        float x0, x1, x2, x3;
        gather_h(g_y1h, ed.x, lane, x0, x1, x2, x3);
        ax += nm * x0; ay += nm * x1; az += nm * x2; aw += nm * x3;
    }
    g_y2[(size_t)node * FV + lane] = make_float4(ax, ay, az, aw);
}

// ---------------- dense linear: out = g_y2 @ W^T + b -----------------------
// Block: 256 threads, tile 64 rows x 128 cols. Thread = 8 rows x 4 cols.
#define GM_TM 64
#define GM_KT 16
__global__ void __launch_bounds__(256) gemm_kernel(const float4* __restrict__ Wm4,
                                                   const float* __restrict__ bias,
                                                   float* __restrict__ out) {
    __shared__ float xs[GM_KT][GM_TM + 1];   // [k][row], padded
    __shared__ float ws[GM_KT][F];           // [k][ocol]
    int t  = threadIdx.x;
    int ci = t & 31;     // col group -> cols 4*ci .. 4*ci+3
    int ri = t >> 5;     // row group -> rows 8*ri .. 8*ri+7
    int row0 = blockIdx.x * GM_TM;

    float acc[8][4];
#pragma unroll
    for (int i = 0; i < 8; i++)
#pragma unroll
        for (int j = 0; j < 4; j++) acc[i][j] = 0.0f;

    for (int k0 = 0; k0 < F; k0 += GM_KT) {
        {
            int r  = t >> 2;
            int kq = (t & 3) * 4;
            float4 v = g_y2[(size_t)(row0 + r) * FV + (k0 + kq) / 4];
            xs[kq + 0][r] = v.x; xs[kq + 1][r] = v.y;
            xs[kq + 2][r] = v.z; xs[kq + 3][r] = v.w;
        }
#pragma unroll
        for (int l = 0; l < 2; l++) {
            int idx = t + l * 256;
            int o   = idx >> 2;
            int kq  = (idx & 3) * 4;
            float4 v = Wm4[((size_t)o * F + k0 + kq) / 4];
            ws[kq + 0][o] = v.x; ws[kq + 1][o] = v.y;
            ws[kq + 2][o] = v.z; ws[kq + 3][o] = v.w;
        }
        __syncthreads();
#pragma unroll
        for (int kk = 0; kk < GM_KT; kk++) {
            float a[8];
#pragma unroll
            for (int j = 0; j < 8; j++) a[j] = xs[kk][ri * 8 + j];       // broadcast
            float b0 = ws[kk][ci * 4 + 0];
            float b1 = ws[kk][ci * 4 + 1];
            float b2 = ws[kk][ci * 4 + 2];
            float b3 = ws[kk][ci * 4 + 3];
#pragma unroll
            for (int i = 0; i < 8; i++) {
                acc[i][0] += a[i] * b0;
                acc[i][1] += a[i] * b1;
                acc[i][2] += a[i] * b2;
                acc[i][3] += a[i] * b3;
            }
        }
        __syncthreads();
    }

#pragma unroll
    for (int i = 0; i < 8; i++) {
        int r = row0 + ri * 8 + i;
        int c = ci * 4;
        float4 v = make_float4(acc[i][0] + bias[c + 0], acc[i][1] + bias[c + 1],
                               acc[i][2] + bias[c + 2], acc[i][3] + bias[c + 3]);
        *(float4*)&out[(size_t)r * F + c] = v;
    }
}

// ---------------------------------------------------------------------------
extern "C" void kernel_launch(void* const* d_in, const int* in_sizes, int n_in,
                              void* d_out, int out_size) {
    const float* x   = (const float*)d_in[0];
    const int*   e32 = (const int*)d_in[1];    // edge_index, width auto-detected
    const float* w   = (const float*)d_in[2];
    const float* Wm  = (const float*)d_in[3];
    const float* b   = (const float*)d_in[4];
    float* out = (float*)d_out;

    const int TB = 256;
    init_kernel<<<(N_NODES + TB - 1) / TB, TB>>>(e32);
    tohalf_kernel<<<(N_NODES * FV + TB - 1) / TB, TB>>>((const float4*)x);
    deg_kernel<<<(N_EDGES + TB - 1) / TB, TB>>>(e32, w);
    dis_kernel<<<(N_NODES + TB - 1) / TB, TB>>>();
    scan_kernel<<<1, 1024>>>();
    scatter_kernel<<<(N_EDGES + TB - 1) / TB, TB>>>(e32, w);

    // two propagation hops (warp per node, 8 warps per block)
    prop1_kernel<<<N_NODES / 8, 256>>>();
    prop2_kernel<<<N_NODES / 8, 256>>>();

    gemm_kernel<<<N_NODES / GM_TM, 256>>>((const float4*)Wm, b, out);
}